// round 12
// baseline (speedup 1.0000x reference)
#include <cuda_runtime.h>
#include <cuda_bf16.h>

#define E_TOTAL 1000000
#define THREADS 288
#define TILE_E  288
#define NTILES  ((E_TOTAL + TILE_E - 1) / TILE_E)
#define GRID    152
#define LN_EPS  1e-5f

typedef unsigned int u32;

// ---- SMEM byte offsets (all 16B aligned) ----
// weights transposed [n][k] bf16, padded strides (halves): W1 104, W2 168, W3 72
#define W1H 0
#define W1L 13312
#define W2H 26624
#define W2L 48128
#define W3H 69632
#define W3L 74240
#define X0H 78848       // x0 hi only, [288][104] bf16
#define HH  138752      // h hi [288][72] bf16 (h1 then h2)
#define HL  180224      // h lo
#define LNP 221696      // 416 floats: b1,g1,be1,b2,g2,be2 (64 each), b3 (32)
#define SMEM_TOTAL (221696 + 416*4)   // 223360

__device__ __forceinline__ u32 smem_u32(const void* p) {
    u32 a;
    asm("{ .reg .u64 t; cvta.to.shared.u64 t, %1; cvt.u32.u64 %0, t; }" : "=r"(a) : "l"(p));
    return a;
}
__device__ __forceinline__ void ldmx4(u32 r[4], u32 addr) {
    asm volatile("ldmatrix.sync.aligned.m8n8.x4.shared.b16 {%0,%1,%2,%3}, [%4];"
                 : "=r"(r[0]), "=r"(r[1]), "=r"(r[2]), "=r"(r[3]) : "r"(addr));
}
__device__ __forceinline__ void mmabf(float c[4], const u32 a[4], u32 b0, u32 b1) {
    asm volatile(
        "mma.sync.aligned.m16n8k16.row.col.f32.bf16.bf16.f32 "
        "{%0,%1,%2,%3}, {%4,%5,%6,%7}, {%8,%9}, {%0,%1,%2,%3};"
        : "+f"(c[0]), "+f"(c[1]), "+f"(c[2]), "+f"(c[3])
        : "r"(a[0]), "r"(a[1]), "r"(a[2]), "r"(a[3]), "r"(b0), "r"(b1));
}
__device__ __forceinline__ void bfsplit(float x, unsigned short &h, unsigned short &l) {
    __nv_bfloat16 hb = __float2bfloat16(x);
    float rem = x - __bfloat162float(hb);
    __nv_bfloat16 lb = __float2bfloat16(rem);
    h = __bfloat16_as_ushort(hb);
    l = __bfloat16_as_ushort(lb);
}
__device__ __forceinline__ u32 pk(unsigned short a, unsigned short b) {
    return (u32)a | ((u32)b << 16);
}
// x0 concat fetch: col in [0,96) -> src/dest/edge_attr
__device__ __forceinline__ float2 x0f2(const float* __restrict__ s, const float* __restrict__ d,
                                       const float* __restrict__ e, int ge, int c) {
    if (ge >= E_TOTAL) return make_float2(0.f, 0.f);
    const float* g = (c < 32) ? s : (c < 64) ? d : e;
    return *(const float2*)(g + (size_t)ge * 32 + (c & 31));
}
// pack the lo-split of a float2
__device__ __forceinline__ u32 lo2(float2 v) {
    unsigned short h, l0, l1;
    bfsplit(v.x, h, l0);
    bfsplit(v.y, h, l1);
    return pk(l0, l1);
}

// relu -> LN(64) -> bf16 hi/lo -> h buffer (stride 72 halves). rowbase = warp-block row.
__device__ __forceinline__ void ln_epilogue(
    float c[8][4], const float* __restrict__ lnb, const float* __restrict__ lng,
    const float* __restrict__ lnbe, char* smem, int rowbase, int lane)
{
    const int tg = lane & 3, gid = lane >> 2;
    float vA[16], vB[16], sA = 0.f, qA = 0.f, sB = 0.f, qB = 0.f;
#pragma unroll
    for (int j = 0; j < 8; j++) {
        int col = 8 * j + 2 * tg;
        float b0 = lnb[col], b1 = lnb[col + 1];
        float a0 = fmaxf(c[j][0] + b0, 0.f), a1 = fmaxf(c[j][1] + b1, 0.f);
        float d0 = fmaxf(c[j][2] + b0, 0.f), d1 = fmaxf(c[j][3] + b1, 0.f);
        vA[2 * j] = a0; vA[2 * j + 1] = a1;
        vB[2 * j] = d0; vB[2 * j + 1] = d1;
        sA += a0 + a1; qA += a0 * a0 + a1 * a1;
        sB += d0 + d1; qB += d0 * d0 + d1 * d1;
    }
#pragma unroll
    for (int m = 1; m < 4; m <<= 1) {
        sA += __shfl_xor_sync(0xffffffffu, sA, m);
        qA += __shfl_xor_sync(0xffffffffu, qA, m);
        sB += __shfl_xor_sync(0xffffffffu, sB, m);
        qB += __shfl_xor_sync(0xffffffffu, qB, m);
    }
    float mA = sA * (1.f / 64.f), mB = sB * (1.f / 64.f);
    float rA = rsqrtf(qA * (1.f / 64.f) - mA * mA + LN_EPS);
    float rB = rsqrtf(qB * (1.f / 64.f) - mB * mB + LN_EPS);
    const int rowA = rowbase + gid, rowB = rowA + 8;
#pragma unroll
    for (int j = 0; j < 8; j++) {
        int col = 8 * j + 2 * tg;
        float g0 = lng[col], g1v = lng[col + 1];
        float p0 = lnbe[col], p1 = lnbe[col + 1];
        float yA0 = (vA[2 * j] - mA) * rA * g0 + p0;
        float yA1 = (vA[2 * j + 1] - mA) * rA * g1v + p1;
        float yB0 = (vB[2 * j] - mB) * rB * g0 + p0;
        float yB1 = (vB[2 * j + 1] - mB) * rB * g1v + p1;
        unsigned short h0, l0, h1, l1;
        bfsplit(yA0, h0, l0); bfsplit(yA1, h1, l1);
        *(u32*)(smem + HH + (rowA * 72 + col) * 2) = pk(h0, h1);
        *(u32*)(smem + HL + (rowA * 72 + col) * 2) = pk(l0, l1);
        bfsplit(yB0, h0, l0); bfsplit(yB1, h1, l1);
        *(u32*)(smem + HH + (rowB * 72 + col) * 2) = pk(h0, h1);
        *(u32*)(smem + HL + (rowB * 72 + col) * 2) = pk(l0, l1);
    }
}

__global__ __launch_bounds__(THREADS, 1)
void EdgeModel_48636209660177_kernel(
    const float* __restrict__ src, const float* __restrict__ dst,
    const float* __restrict__ ea,
    const float* __restrict__ W1, const float* __restrict__ b1,
    const float* __restrict__ g1, const float* __restrict__ be1,
    const float* __restrict__ W2, const float* __restrict__ b2,
    const float* __restrict__ g2, const float* __restrict__ be2,
    const float* __restrict__ W3, const float* __restrict__ b3,
    float* __restrict__ out)
{
    extern __shared__ char smem[];
    const u32 smb = smem_u32(smem);
    const int tid = threadIdx.x, lane = tid & 31, warp = tid >> 5;
    float* lnp = (float*)(smem + LNP);

    // ---- one-time: weights -> transposed bf16 hi/lo; LN params -> smem ----
    for (int i = tid; i < 96 * 64; i += THREADS) {
        int k = i >> 6, n = i & 63;
        unsigned short h, l; bfsplit(__ldg(&W1[i]), h, l);
        int off = (n * 104 + k) * 2;
        *(unsigned short*)(smem + W1H + off) = h;
        *(unsigned short*)(smem + W1L + off) = l;
    }
    for (int i = tid; i < 160 * 64; i += THREADS) {
        int k = i >> 6, n = i & 63;
        unsigned short h, l; bfsplit(__ldg(&W2[i]), h, l);
        int off = (n * 168 + k) * 2;
        *(unsigned short*)(smem + W2H + off) = h;
        *(unsigned short*)(smem + W2L + off) = l;
    }
    for (int i = tid; i < 64 * 32; i += THREADS) {
        int k = i >> 5, n = i & 31;
        unsigned short h, l; bfsplit(__ldg(&W3[i]), h, l);
        int off = (n * 72 + k) * 2;
        *(unsigned short*)(smem + W3H + off) = h;
        *(unsigned short*)(smem + W3L + off) = l;
    }
    for (int i = tid; i < 64; i += THREADS) {
        lnp[i] = b1[i]; lnp[64 + i] = g1[i]; lnp[128 + i] = be1[i];
        lnp[192 + i] = b2[i]; lnp[256 + i] = g2[i]; lnp[320 + i] = be2[i];
    }
    for (int i = tid; i < 32; i += THREADS) lnp[384 + i] = b3[i];
    __syncthreads();

    const int e0 = warp * 32;                 // this warp's 32 edge rows (fixed)
    const int tg = lane & 3, gid = lane >> 2;
    const int arow = lane & 15, asel = lane >> 4;       // A ldmatrix addressing
    const int brow = ((lane >> 4) << 3) + (lane & 7);   // B pair-x4 addressing
    const int boff = ((lane >> 3) & 1) * 16;

    for (int tile = blockIdx.x; tile < NTILES; tile += GRID) {
        const int eb = tile * TILE_E;

        // ---- stage own 32 edges of x0 hi into smem ([e][k] stride 104) ----
        for (int i = lane; i < 32 * 24; i += 32) {
            int el = i / 24, s = i % 24;
            int ge = eb + e0 + el;
            const float* g = (s < 8) ? src : (s < 16) ? dst : ea;
            int seg = s & 7;
            float4 v = make_float4(0.f, 0.f, 0.f, 0.f);
            if (ge < E_TOTAL) v = *(const float4*)(g + (size_t)ge * 32 + seg * 4);
            int col = (s >> 3) * 32 + seg * 4;
            unsigned short hx, lx, hy, ly, hz, lz, hw, lw;
            bfsplit(v.x, hx, lx); bfsplit(v.y, hy, ly);
            bfsplit(v.z, hz, lz); bfsplit(v.w, hw, lw);
            *(uint2*)(smem + X0H + ((e0 + el) * 104 + col) * 2) =
                make_uint2(pk(hx, hy), pk(hz, hw));
        }

        // ---- x0 lo-split A-fragments straight into registers (L2-hot reload) ----
        u32 x0lo[2][6][4];
#pragma unroll
        for (int blk = 0; blk < 2; blk++) {
            int r0 = eb + e0 + blk * 16 + gid;
            int r1 = r0 + 8;
#pragma unroll
            for (int ks = 0; ks < 6; ks++) {
                int k0 = ks * 16 + 2 * tg;
                x0lo[blk][ks][0] = lo2(x0f2(src, dst, ea, r0, k0));
                x0lo[blk][ks][1] = lo2(x0f2(src, dst, ea, r1, k0));
                x0lo[blk][ks][2] = lo2(x0f2(src, dst, ea, r0, k0 + 8));
                x0lo[blk][ks][3] = lo2(x0f2(src, dst, ea, r1, k0 + 8));
            }
        }
        __syncwarp();

        float c[2][8][4];

        // ================= layer 1: x0[96] @ W1 -> 64 =================
#pragma unroll
        for (int blk = 0; blk < 2; blk++)
#pragma unroll
            for (int j = 0; j < 8; j++)
#pragma unroll
                for (int q = 0; q < 4; q++) c[blk][j][q] = 0.f;
#pragma unroll
        for (int ks = 0; ks < 6; ks++) {
            int k0 = ks * 16;
            u32 aH0[4], aH1[4];
            ldmx4(aH0, smb + X0H + ((e0 + arow) * 104 + k0 + asel * 8) * 2);
            ldmx4(aH1, smb + X0H + ((e0 + 16 + arow) * 104 + k0 + asel * 8) * 2);
#pragma unroll
            for (int jp = 0; jp < 8; jp += 2) {
                u32 addr = ((jp * 8 + brow) * 104 + k0) * 2 + boff;
                u32 bH[4], bL[4];
                ldmx4(bH, smb + W1H + addr);
                ldmx4(bL, smb + W1L + addr);
                mmabf(c[0][jp], aH0, bH[0], bH[1]);
                mmabf(c[0][jp], aH0, bL[0], bL[1]);
                mmabf(c[0][jp], x0lo[0][ks], bH[0], bH[1]);
                mmabf(c[0][jp + 1], aH0, bH[2], bH[3]);
                mmabf(c[0][jp + 1], aH0, bL[2], bL[3]);
                mmabf(c[0][jp + 1], x0lo[0][ks], bH[2], bH[3]);
                mmabf(c[1][jp], aH1, bH[0], bH[1]);
                mmabf(c[1][jp], aH1, bL[0], bL[1]);
                mmabf(c[1][jp], x0lo[1][ks], bH[0], bH[1]);
                mmabf(c[1][jp + 1], aH1, bH[2], bH[3]);
                mmabf(c[1][jp + 1], aH1, bL[2], bL[3]);
                mmabf(c[1][jp + 1], x0lo[1][ks], bH[2], bH[3]);
            }
        }
        ln_epilogue(c[0], lnp, lnp + 64, lnp + 128, smem, e0, lane);
        ln_epilogue(c[1], lnp, lnp + 64, lnp + 128, smem, e0 + 16, lane);
        __syncwarp();

        // ================= layer 2: [h1(64), x0(96)] @ W2 -> 64 =================
#pragma unroll
        for (int blk = 0; blk < 2; blk++)
#pragma unroll
            for (int j = 0; j < 8; j++)
#pragma unroll
                for (int q = 0; q < 4; q++) c[blk][j][q] = 0.f;
#pragma unroll
        for (int ks = 0; ks < 10; ks++) {
            int kb = ks * 16;
            u32 aH0[4], aH1[4], aL0[4], aL1[4];
            const u32* pL0;
            const u32* pL1;
            if (ks < 4) {
                u32 o0 = ((e0 + arow) * 72 + kb + asel * 8) * 2;
                u32 o1 = ((e0 + 16 + arow) * 72 + kb + asel * 8) * 2;
                ldmx4(aH0, smb + HH + o0);
                ldmx4(aH1, smb + HH + o1);
                ldmx4(aL0, smb + HL + o0);
                ldmx4(aL1, smb + HL + o1);
                pL0 = aL0; pL1 = aL1;
            } else {
                int kx = kb - 64;
                ldmx4(aH0, smb + X0H + ((e0 + arow) * 104 + kx + asel * 8) * 2);
                ldmx4(aH1, smb + X0H + ((e0 + 16 + arow) * 104 + kx + asel * 8) * 2);
                pL0 = x0lo[0][ks - 4]; pL1 = x0lo[1][ks - 4];
            }
#pragma unroll
            for (int jp = 0; jp < 8; jp += 2) {
                u32 addr = ((jp * 8 + brow) * 168 + kb) * 2 + boff;
                u32 bH[4], bL[4];
                ldmx4(bH, smb + W2H + addr);
                ldmx4(bL, smb + W2L + addr);
                mmabf(c[0][jp], aH0, bH[0], bH[1]);
                mmabf(c[0][jp], aH0, bL[0], bL[1]);
                mmabf(c[0][jp], pL0, bH[0], bH[1]);
                mmabf(c[0][jp + 1], aH0, bH[2], bH[3]);
                mmabf(c[0][jp + 1], aH0, bL[2], bL[3]);
                mmabf(c[0][jp + 1], pL0, bH[2], bH[3]);
                mmabf(c[1][jp], aH1, bH[0], bH[1]);
                mmabf(c[1][jp], aH1, bL[0], bL[1]);
                mmabf(c[1][jp], pL1, bH[0], bH[1]);
                mmabf(c[1][jp + 1], aH1, bH[2], bH[3]);
                mmabf(c[1][jp + 1], aH1, bL[2], bL[3]);
                mmabf(c[1][jp + 1], pL1, bH[2], bH[3]);
            }
        }
        ln_epilogue(c[0], lnp + 192, lnp + 256, lnp + 320, smem, e0, lane);
        ln_epilogue(c[1], lnp + 192, lnp + 256, lnp + 320, smem, e0 + 16, lane);
        __syncwarp();

        // ================= layer 3: h2[64] @ W3 -> 32, + b3 -> gmem =================
        {
            float c3[2][4][4];
#pragma unroll
            for (int blk = 0; blk < 2; blk++)
#pragma unroll
                for (int j = 0; j < 4; j++)
#pragma unroll
                    for (int q = 0; q < 4; q++) c3[blk][j][q] = 0.f;
#pragma unroll
            for (int ks = 0; ks < 4; ks++) {
                int k0 = ks * 16;
                u32 aH0[4], aH1[4], aL0[4], aL1[4];
                u32 o0 = ((e0 + arow) * 72 + k0 + asel * 8) * 2;
                u32 o1 = ((e0 + 16 + arow) * 72 + k0 + asel * 8) * 2;
                ldmx4(aH0, smb + HH + o0);
                ldmx4(aH1, smb + HH + o1);
                ldmx4(aL0, smb + HL + o0);
                ldmx4(aL1, smb + HL + o1);
#pragma unroll
                for (int jp = 0; jp < 4; jp += 2) {
                    u32 addr = ((jp * 8 + brow) * 72 + k0) * 2 + boff;
                    u32 bH[4], bL[4];
                    ldmx4(bH, smb + W3H + addr);
                    ldmx4(bL, smb + W3L + addr);
                    mmabf(c3[0][jp], aH0, bH[0], bH[1]);
                    mmabf(c3[0][jp], aH0, bL[0], bL[1]);
                    mmabf(c3[0][jp], aL0, bH[0], bH[1]);
                    mmabf(c3[0][jp + 1], aH0, bH[2], bH[3]);
                    mmabf(c3[0][jp + 1], aH0, bL[2], bL[3]);
                    mmabf(c3[0][jp + 1], aL0, bH[2], bH[3]);
                    mmabf(c3[1][jp], aH1, bH[0], bH[1]);
                    mmabf(c3[1][jp], aH1, bL[0], bL[1]);
                    mmabf(c3[1][jp], aL1, bH[0], bH[1]);
                    mmabf(c3[1][jp + 1], aH1, bH[2], bH[3]);
                    mmabf(c3[1][jp + 1], aH1, bL[2], bL[3]);
                    mmabf(c3[1][jp + 1], aL1, bH[2], bH[3]);
                }
            }
#pragma unroll
            for (int blk = 0; blk < 2; blk++) {
                int geA = eb + e0 + blk * 16 + gid, geB = geA + 8;
#pragma unroll
                for (int j = 0; j < 4; j++) {
                    int col = 8 * j + 2 * tg;
                    float bb0 = lnp[384 + col], bb1 = lnp[384 + col + 1];
                    if (geA < E_TOTAL)
                        *(float2*)(out + (size_t)geA * 32 + col) =
                            make_float2(c3[blk][j][0] + bb0, c3[blk][j][1] + bb1);
                    if (geB < E_TOTAL)
                        *(float2*)(out + (size_t)geB * 32 + col) =
                            make_float2(c3[blk][j][2] + bb0, c3[blk][j][3] + bb1);
                }
            }
        }
        __syncwarp();
    }
}

extern "C" void kernel_launch(void* const* d_in, const int* in_sizes, int n_in,
                              void* d_out, int out_size) {
    (void)in_sizes; (void)n_in; (void)out_size;
    const float* src = (const float*)d_in[0];
    const float* dst = (const float*)d_in[1];
    const float* ea  = (const float*)d_in[2];
    const float* W1  = (const float*)d_in[3];
    const float* b1  = (const float*)d_in[4];
    const float* g1  = (const float*)d_in[5];
    const float* be1 = (const float*)d_in[6];
    const float* W2  = (const float*)d_in[7];
    const float* b2  = (const float*)d_in[8];
    const float* g2  = (const float*)d_in[9];
    const float* be2 = (const float*)d_in[10];
    const float* W3  = (const float*)d_in[11];
    const float* b3  = (const float*)d_in[12];
    float* out = (float*)d_out;

    cudaFuncSetAttribute(EdgeModel_48636209660177_kernel,
                         cudaFuncAttributeMaxDynamicSharedMemorySize, SMEM_TOTAL);
    EdgeModel_48636209660177_kernel<<<GRID, THREADS, SMEM_TOTAL>>>(
        src, dst, ea, W1, b1, g1, be1, W2, b2, g2, be2, W3, b3, out);
}

// round 13
// speedup vs baseline: 1.3734x; 1.3734x over previous
#include <cuda_runtime.h>
#include <cuda_bf16.h>

#define E_TOTAL 1000000
#define THREADS 448
#define TILE_E  224
#define NTILES  ((E_TOTAL + TILE_E - 1) / TILE_E)
#define GRID    152
#define LN_EPS  1e-5f

typedef unsigned int u32;

// ---- SMEM byte offsets ----
// weights transposed [n][k] bf16, padded strides (halves): W1 104, W2 168, W3 72
#define W1H 0
#define W1L 13312
#define W2H 26624
#define W2L 48128
#define W3H 69632
#define W3L 74240
#define X0H 78848       // x0 hi only, [224][104] bf16
#define LNP 125440      // 416 floats: b1,g1,be1,b2,g2,be2 (64 each), b3 (32)
#define SMEM_TOTAL (125440 + 416*4)   // 127104

__device__ __forceinline__ u32 smem_u32(const void* p) {
    u32 a;
    asm("{ .reg .u64 t; cvta.to.shared.u64 t, %1; cvt.u32.u64 %0, t; }" : "=r"(a) : "l"(p));
    return a;
}
__device__ __forceinline__ void ldmx4(u32 r[4], u32 addr) {
    asm volatile("ldmatrix.sync.aligned.m8n8.x4.shared.b16 {%0,%1,%2,%3}, [%4];"
                 : "=r"(r[0]), "=r"(r[1]), "=r"(r[2]), "=r"(r[3]) : "r"(addr));
}
__device__ __forceinline__ void mmabf(float c[4], const u32 a[4], u32 b0, u32 b1) {
    asm volatile(
        "mma.sync.aligned.m16n8k16.row.col.f32.bf16.bf16.f32 "
        "{%0,%1,%2,%3}, {%4,%5,%6,%7}, {%8,%9}, {%0,%1,%2,%3};"
        : "+f"(c[0]), "+f"(c[1]), "+f"(c[2]), "+f"(c[3])
        : "r"(a[0]), "r"(a[1]), "r"(a[2]), "r"(a[3]), "r"(b0), "r"(b1));
}
__device__ __forceinline__ void bfsplit(float x, unsigned short &h, unsigned short &l) {
    __nv_bfloat16 hb = __float2bfloat16(x);
    float rem = x - __bfloat162float(hb);
    __nv_bfloat16 lb = __float2bfloat16(rem);
    h = __bfloat16_as_ushort(hb);
    l = __bfloat16_as_ushort(lb);
}
__device__ __forceinline__ u32 pk(unsigned short a, unsigned short b) {
    return (u32)a | ((u32)b << 16);
}
// x0 concat fetch: col in [0,96) -> src/dest/edge_attr
__device__ __forceinline__ float2 x0f2(const float* __restrict__ s, const float* __restrict__ d,
                                       const float* __restrict__ e, int ge, int c) {
    if (ge >= E_TOTAL) return make_float2(0.f, 0.f);
    const float* g = (c < 32) ? s : (c < 64) ? d : e;
    return *(const float2*)(g + (size_t)ge * 32 + (c & 31));
}
__device__ __forceinline__ u32 lo2(float2 v) {
    unsigned short h, l0, l1;
    bfsplit(v.x, h, l0);
    bfsplit(v.y, h, l1);
    return pk(l0, l1);
}

// relu -> LN(64) -> bf16 hi/lo A-fragments (4 k-steps) entirely in registers.
// Thread (tg,gid) owns rows gid/gid+8, cols 8j+2tg — exactly the mma fragment set.
__device__ __forceinline__ void ln_frag(
    const float c[8][4], const float* __restrict__ lnb, const float* __restrict__ lng,
    const float* __restrict__ lnbe, u32 fh[4][4], u32 fl[4][4], int lane)
{
    const int tg = lane & 3;
    float vA[16], vB[16], sA = 0.f, qA = 0.f, sB = 0.f, qB = 0.f;
#pragma unroll
    for (int j = 0; j < 8; j++) {
        int col = 8 * j + 2 * tg;
        float b0 = lnb[col], b1 = lnb[col + 1];
        float a0 = fmaxf(c[j][0] + b0, 0.f), a1 = fmaxf(c[j][1] + b1, 0.f);
        float d0 = fmaxf(c[j][2] + b0, 0.f), d1 = fmaxf(c[j][3] + b1, 0.f);
        vA[2 * j] = a0; vA[2 * j + 1] = a1;
        vB[2 * j] = d0; vB[2 * j + 1] = d1;
        sA += a0 + a1; qA += a0 * a0 + a1 * a1;
        sB += d0 + d1; qB += d0 * d0 + d1 * d1;
    }
#pragma unroll
    for (int m = 1; m < 4; m <<= 1) {
        sA += __shfl_xor_sync(0xffffffffu, sA, m);
        qA += __shfl_xor_sync(0xffffffffu, qA, m);
        sB += __shfl_xor_sync(0xffffffffu, sB, m);
        qB += __shfl_xor_sync(0xffffffffu, qB, m);
    }
    float mA = sA * (1.f / 64.f), mB = sB * (1.f / 64.f);
    float rA = rsqrtf(qA * (1.f / 64.f) - mA * mA + LN_EPS);
    float rB = rsqrtf(qB * (1.f / 64.f) - mB * mB + LN_EPS);
#pragma unroll
    for (int ks = 0; ks < 4; ks++) {
        // j = 2ks (cols 16ks+2tg,+1), j = 2ks+1 (cols 16ks+8+2tg,+1)
        int c0 = 16 * ks + 2 * tg, c1 = c0 + 8;
        float g0 = lng[c0], g1v = lng[c0 + 1], g2v = lng[c1], g3 = lng[c1 + 1];
        float p0 = lnbe[c0], p1 = lnbe[c0 + 1], p2 = lnbe[c1], p3 = lnbe[c1 + 1];
        float yA0 = (vA[4 * ks] - mA) * rA * g0 + p0;
        float yA1 = (vA[4 * ks + 1] - mA) * rA * g1v + p1;
        float yA2 = (vA[4 * ks + 2] - mA) * rA * g2v + p2;
        float yA3 = (vA[4 * ks + 3] - mA) * rA * g3 + p3;
        float yB0 = (vB[4 * ks] - mB) * rB * g0 + p0;
        float yB1 = (vB[4 * ks + 1] - mB) * rB * g1v + p1;
        float yB2 = (vB[4 * ks + 2] - mB) * rB * g2v + p2;
        float yB3 = (vB[4 * ks + 3] - mB) * rB * g3 + p3;
        unsigned short h0, l0, h1, l1;
        bfsplit(yA0, h0, l0); bfsplit(yA1, h1, l1);
        fh[ks][0] = pk(h0, h1); fl[ks][0] = pk(l0, l1);
        bfsplit(yB0, h0, l0); bfsplit(yB1, h1, l1);
        fh[ks][1] = pk(h0, h1); fl[ks][1] = pk(l0, l1);
        bfsplit(yA2, h0, l0); bfsplit(yA3, h1, l1);
        fh[ks][2] = pk(h0, h1); fl[ks][2] = pk(l0, l1);
        bfsplit(yB2, h0, l0); bfsplit(yB3, h1, l1);
        fh[ks][3] = pk(h0, h1); fl[ks][3] = pk(l0, l1);
    }
}

__global__ __launch_bounds__(THREADS, 1)
void EdgeModel_48636209660177_kernel(
    const float* __restrict__ src, const float* __restrict__ dst,
    const float* __restrict__ ea,
    const float* __restrict__ W1, const float* __restrict__ b1,
    const float* __restrict__ g1, const float* __restrict__ be1,
    const float* __restrict__ W2, const float* __restrict__ b2,
    const float* __restrict__ g2, const float* __restrict__ be2,
    const float* __restrict__ W3, const float* __restrict__ b3,
    float* __restrict__ out)
{
    extern __shared__ char smem[];
    const u32 smb = smem_u32(smem);
    const int tid = threadIdx.x, lane = tid & 31, warp = tid >> 5;
    float* lnp = (float*)(smem + LNP);

    // ---- one-time: weights -> transposed bf16 hi/lo; LN params -> smem ----
    for (int i = tid; i < 96 * 64; i += THREADS) {
        int k = i >> 6, n = i & 63;
        unsigned short h, l; bfsplit(__ldg(&W1[i]), h, l);
        int off = (n * 104 + k) * 2;
        *(unsigned short*)(smem + W1H + off) = h;
        *(unsigned short*)(smem + W1L + off) = l;
    }
    for (int i = tid; i < 160 * 64; i += THREADS) {
        int k = i >> 6, n = i & 63;
        unsigned short h, l; bfsplit(__ldg(&W2[i]), h, l);
        int off = (n * 168 + k) * 2;
        *(unsigned short*)(smem + W2H + off) = h;
        *(unsigned short*)(smem + W2L + off) = l;
    }
    for (int i = tid; i < 64 * 32; i += THREADS) {
        int k = i >> 5, n = i & 31;
        unsigned short h, l; bfsplit(__ldg(&W3[i]), h, l);
        int off = (n * 72 + k) * 2;
        *(unsigned short*)(smem + W3H + off) = h;
        *(unsigned short*)(smem + W3L + off) = l;
    }
    for (int i = tid; i < 64; i += THREADS) {
        lnp[i] = b1[i]; lnp[64 + i] = g1[i]; lnp[128 + i] = be1[i];
        lnp[192 + i] = b2[i]; lnp[256 + i] = g2[i]; lnp[320 + i] = be2[i];
    }
    for (int i = tid; i < 32; i += THREADS) lnp[384 + i] = b3[i];
    __syncthreads();

    const int e0 = warp * 16;                 // this warp's 16 edge rows (fixed)
    const int tg = lane & 3, gid = lane >> 2;
    const int arow = lane & 15, asel = lane >> 4;       // A ldmatrix addressing
    const int brow = ((lane >> 4) << 3) + (lane & 7);   // B pair-x4 addressing
    const int boff = ((lane >> 3) & 1) * 16;

    for (int tile = blockIdx.x; tile < NTILES; tile += GRID) {
        const int eb = tile * TILE_E;
        __syncwarp();   // prior tile's x0H ldmatrix reads complete before overwrite

        // ---- stage own 16 edges of x0 hi into smem ([e][k] stride 104) ----
        for (int i = lane; i < 16 * 24; i += 32) {
            int el = i / 24, s = i % 24;
            int ge = eb + e0 + el;
            const float* g = (s < 8) ? src : (s < 16) ? dst : ea;
            int seg = s & 7;
            float4 v = make_float4(0.f, 0.f, 0.f, 0.f);
            if (ge < E_TOTAL) v = *(const float4*)(g + (size_t)ge * 32 + seg * 4);
            int col = (s >> 3) * 32 + seg * 4;
            unsigned short hx, lx, hy, ly, hz, lz, hw, lw;
            bfsplit(v.x, hx, lx); bfsplit(v.y, hy, ly);
            bfsplit(v.z, hz, lz); bfsplit(v.w, hw, lw);
            *(uint2*)(smem + X0H + ((e0 + el) * 104 + col) * 2) =
                make_uint2(pk(hx, hy), pk(hz, hw));
        }

        // ---- x0 lo-split A-fragments straight into registers (L2-hot reload) ----
        u32 x0lo[6][4];
        {
            int r0 = eb + e0 + gid, r1 = r0 + 8;
#pragma unroll
            for (int ks = 0; ks < 6; ks++) {
                int k0 = ks * 16 + 2 * tg;
                x0lo[ks][0] = lo2(x0f2(src, dst, ea, r0, k0));
                x0lo[ks][1] = lo2(x0f2(src, dst, ea, r1, k0));
                x0lo[ks][2] = lo2(x0f2(src, dst, ea, r0, k0 + 8));
                x0lo[ks][3] = lo2(x0f2(src, dst, ea, r1, k0 + 8));
            }
        }
        __syncwarp();

        float c[8][4];
        u32 fh[4][4], fl[4][4];

        // ================= layer 1: x0[96] @ W1 -> 64 =================
#pragma unroll
        for (int j = 0; j < 8; j++)
#pragma unroll
            for (int q = 0; q < 4; q++) c[j][q] = 0.f;
#pragma unroll
        for (int ks = 0; ks < 6; ks++) {
            int k0 = ks * 16;
            u32 aH[4];
            ldmx4(aH, smb + X0H + ((e0 + arow) * 104 + k0 + asel * 8) * 2);
#pragma unroll
            for (int jp = 0; jp < 8; jp += 2) {
                u32 addr = ((jp * 8 + brow) * 104 + k0) * 2 + boff;
                u32 bH[4], bL[4];
                ldmx4(bH, smb + W1H + addr);
                ldmx4(bL, smb + W1L + addr);
                mmabf(c[jp], aH, bH[0], bH[1]);
                mmabf(c[jp], aH, bL[0], bL[1]);
                mmabf(c[jp], x0lo[ks], bH[0], bH[1]);
                mmabf(c[jp + 1], aH, bH[2], bH[3]);
                mmabf(c[jp + 1], aH, bL[2], bL[3]);
                mmabf(c[jp + 1], x0lo[ks], bH[2], bH[3]);
            }
        }
        ln_frag(c, lnp, lnp + 64, lnp + 128, fh, fl, lane);

        // ================= layer 2: [h1(64), x0(96)] @ W2 -> 64 =================
#pragma unroll
        for (int j = 0; j < 8; j++)
#pragma unroll
            for (int q = 0; q < 4; q++) c[j][q] = 0.f;
#pragma unroll
        for (int ks = 0; ks < 10; ks++) {
            int kb = ks * 16;
            u32 aHbuf[4];
            const u32 *pH, *pL;
            if (ks < 4) {
                pH = fh[ks]; pL = fl[ks];
            } else {
                ldmx4(aHbuf, smb + X0H + ((e0 + arow) * 104 + (kb - 64) + asel * 8) * 2);
                pH = aHbuf; pL = x0lo[ks - 4];
            }
#pragma unroll
            for (int jp = 0; jp < 8; jp += 2) {
                u32 addr = ((jp * 8 + brow) * 168 + kb) * 2 + boff;
                u32 bH[4], bL[4];
                ldmx4(bH, smb + W2H + addr);
                ldmx4(bL, smb + W2L + addr);
                mmabf(c[jp], pH, bH[0], bH[1]);
                mmabf(c[jp], pH, bL[0], bL[1]);
                mmabf(c[jp], pL, bH[0], bH[1]);
                mmabf(c[jp + 1], pH, bH[2], bH[3]);
                mmabf(c[jp + 1], pH, bL[2], bL[3]);
                mmabf(c[jp + 1], pL, bH[2], bH[3]);
            }
        }
        ln_frag(c, lnp + 192, lnp + 256, lnp + 320, fh, fl, lane);

        // ================= layer 3: h2[64] @ W3 -> 32, + b3 -> gmem =================
        {
            float c3[4][4];
#pragma unroll
            for (int j = 0; j < 4; j++)
#pragma unroll
                for (int q = 0; q < 4; q++) c3[j][q] = 0.f;
#pragma unroll
            for (int ks = 0; ks < 4; ks++) {
                int k0 = ks * 16;
#pragma unroll
                for (int jp = 0; jp < 4; jp += 2) {
                    u32 addr = ((jp * 8 + brow) * 72 + k0) * 2 + boff;
                    u32 bH[4], bL[4];
                    ldmx4(bH, smb + W3H + addr);
                    ldmx4(bL, smb + W3L + addr);
                    mmabf(c3[jp], fh[ks], bH[0], bH[1]);
                    mmabf(c3[jp], fh[ks], bL[0], bL[1]);
                    mmabf(c3[jp], fl[ks], bH[0], bH[1]);
                    mmabf(c3[jp + 1], fh[ks], bH[2], bH[3]);
                    mmabf(c3[jp + 1], fh[ks], bL[2], bL[3]);
                    mmabf(c3[jp + 1], fl[ks], bH[2], bH[3]);
                }
            }
            int geA = eb + e0 + gid, geB = geA + 8;
#pragma unroll
            for (int j = 0; j < 4; j++) {
                int col = 8 * j + 2 * tg;
                float bb0 = lnp[384 + col], bb1 = lnp[384 + col + 1];
                if (geA < E_TOTAL)
                    *(float2*)(out + (size_t)geA * 32 + col) =
                        make_float2(c3[j][0] + bb0, c3[j][1] + bb1);
                if (geB < E_TOTAL)
                    *(float2*)(out + (size_t)geB * 32 + col) =
                        make_float2(c3[j][2] + bb0, c3[j][3] + bb1);
            }
        }
    }
}

extern "C" void kernel_launch(void* const* d_in, const int* in_sizes, int n_in,
                              void* d_out, int out_size) {
    (void)in_sizes; (void)n_in; (void)out_size;
    const float* src = (const float*)d_in[0];
    const float* dst = (const float*)d_in[1];
    const float* ea  = (const float*)d_in[2];
    const float* W1  = (const float*)d_in[3];
    const float* b1  = (const float*)d_in[4];
    const float* g1  = (const float*)d_in[5];
    const float* be1 = (const float*)d_in[6];
    const float* W2  = (const float*)d_in[7];
    const float* b2  = (const float*)d_in[8];
    const float* g2  = (const float*)d_in[9];
    const float* be2 = (const float*)d_in[10];
    const float* W3  = (const float*)d_in[11];
    const float* b3  = (const float*)d_in[12];
    float* out = (float*)d_out;

    cudaFuncSetAttribute(EdgeModel_48636209660177_kernel,
                         cudaFuncAttributeMaxDynamicSharedMemorySize, SMEM_TOTAL);
    EdgeModel_48636209660177_kernel<<<GRID, THREADS, SMEM_TOTAL>>>(
        src, dst, ea, W1, b1, g1, be1, W2, b2, g2, be2, W3, b3, out);
}

// round 14
// speedup vs baseline: 2.0205x; 1.4712x over previous
#include <cuda_runtime.h>
#include <cuda_fp16.h>

#define E_TOTAL 1000000
#define THREADS 448
#define TILE_E  224
#define NTILES  ((E_TOTAL + TILE_E - 1) / TILE_E)
#define GRID    152
#define LN_EPS  1e-5f

typedef unsigned int u32;
typedef unsigned short u16;

// ---- SMEM byte offsets ----
// weights transposed [n][k] fp16 (hi only), padded strides (halves): W1 104, W2 168, W3 72
#define W1H 0
#define W2H 13312
#define W3H 34816
#define X0H 39424       // x0 hi, [224][104] fp16
#define LNP 86016       // 416 floats: b1,g1,be1,b2,g2,be2 (64 each), b3 (32)
#define SMEM_TOTAL (86016 + 416*4)   // 87680

__device__ __forceinline__ u32 smem_u32(const void* p) {
    u32 a;
    asm("{ .reg .u64 t; cvta.to.shared.u64 t, %1; cvt.u32.u64 %0, t; }" : "=r"(a) : "l"(p));
    return a;
}
__device__ __forceinline__ void ldmx4(u32 r[4], u32 addr) {
    asm volatile("ldmatrix.sync.aligned.m8n8.x4.shared.b16 {%0,%1,%2,%3}, [%4];"
                 : "=r"(r[0]), "=r"(r[1]), "=r"(r[2]), "=r"(r[3]) : "r"(addr));
}
__device__ __forceinline__ void mmafp(float c[4], const u32 a[4], u32 b0, u32 b1) {
    asm volatile(
        "mma.sync.aligned.m16n8k16.row.col.f32.f16.f16.f32 "
        "{%0,%1,%2,%3}, {%4,%5,%6,%7}, {%8,%9}, {%0,%1,%2,%3};"
        : "+f"(c[0]), "+f"(c[1]), "+f"(c[2]), "+f"(c[3])
        : "r"(a[0]), "r"(a[1]), "r"(a[2]), "r"(a[3]), "r"(b0), "r"(b1));
}
// fp16 hi/lo split: x = hi + lo with |lo| ~ 2^-12 |x|
__device__ __forceinline__ void hfsplit(float x, u16 &h, u16 &l) {
    __half hh = __float2half_rn(x);
    float rem = x - __half2float(hh);
    __half ll = __float2half_rn(rem);
    h = __half_as_ushort(hh);
    l = __half_as_ushort(ll);
}
__device__ __forceinline__ u16 hf(float x) {
    __half hh = __float2half_rn(x);
    return __half_as_ushort(hh);
}
__device__ __forceinline__ u32 pk(u16 a, u16 b) {
    return (u32)a | ((u32)b << 16);
}
// x0 concat fetch: col in [0,96) -> src/dest/edge_attr
__device__ __forceinline__ float2 x0f2(const float* __restrict__ s, const float* __restrict__ d,
                                       const float* __restrict__ e, int ge, int c) {
    if (ge >= E_TOTAL) return make_float2(0.f, 0.f);
    const float* g = (c < 32) ? s : (c < 64) ? d : e;
    return *(const float2*)(g + (size_t)ge * 32 + (c & 31));
}
__device__ __forceinline__ u32 lo2(float2 v) {
    u16 h, l0, l1;
    hfsplit(v.x, h, l0);
    hfsplit(v.y, h, l1);
    return pk(l0, l1);
}

// relu -> LN(64) -> fp16 hi/lo A-fragments (4 k-steps) entirely in registers.
// Thread (tg,gid) owns rows gid/gid+8, cols 8j+2tg — exactly the mma fragment set.
__device__ __forceinline__ void ln_frag(
    const float c[8][4], const float* __restrict__ lnb, const float* __restrict__ lng,
    const float* __restrict__ lnbe, u32 fh[4][4], u32 fl[4][4], int lane)
{
    const int tg = lane & 3;
    float vA[16], vB[16], sA = 0.f, qA = 0.f, sB = 0.f, qB = 0.f;
#pragma unroll
    for (int j = 0; j < 8; j++) {
        int col = 8 * j + 2 * tg;
        float b0 = lnb[col], b1 = lnb[col + 1];
        float a0 = fmaxf(c[j][0] + b0, 0.f), a1 = fmaxf(c[j][1] + b1, 0.f);
        float d0 = fmaxf(c[j][2] + b0, 0.f), d1 = fmaxf(c[j][3] + b1, 0.f);
        vA[2 * j] = a0; vA[2 * j + 1] = a1;
        vB[2 * j] = d0; vB[2 * j + 1] = d1;
        sA += a0 + a1; qA += a0 * a0 + a1 * a1;
        sB += d0 + d1; qB += d0 * d0 + d1 * d1;
    }
#pragma unroll
    for (int m = 1; m < 4; m <<= 1) {
        sA += __shfl_xor_sync(0xffffffffu, sA, m);
        qA += __shfl_xor_sync(0xffffffffu, qA, m);
        sB += __shfl_xor_sync(0xffffffffu, sB, m);
        qB += __shfl_xor_sync(0xffffffffu, qB, m);
    }
    float mA = sA * (1.f / 64.f), mB = sB * (1.f / 64.f);
    float rA = rsqrtf(qA * (1.f / 64.f) - mA * mA + LN_EPS);
    float rB = rsqrtf(qB * (1.f / 64.f) - mB * mB + LN_EPS);
#pragma unroll
    for (int ks = 0; ks < 4; ks++) {
        int c0 = 16 * ks + 2 * tg, c1 = c0 + 8;
        float g0 = lng[c0], g1v = lng[c0 + 1], g2v = lng[c1], g3 = lng[c1 + 1];
        float p0 = lnbe[c0], p1 = lnbe[c0 + 1], p2 = lnbe[c1], p3 = lnbe[c1 + 1];
        float yA0 = (vA[4 * ks] - mA) * rA * g0 + p0;
        float yA1 = (vA[4 * ks + 1] - mA) * rA * g1v + p1;
        float yA2 = (vA[4 * ks + 2] - mA) * rA * g2v + p2;
        float yA3 = (vA[4 * ks + 3] - mA) * rA * g3 + p3;
        float yB0 = (vB[4 * ks] - mB) * rB * g0 + p0;
        float yB1 = (vB[4 * ks + 1] - mB) * rB * g1v + p1;
        float yB2 = (vB[4 * ks + 2] - mB) * rB * g2v + p2;
        float yB3 = (vB[4 * ks + 3] - mB) * rB * g3 + p3;
        u16 h0, l0, h1, l1;
        hfsplit(yA0, h0, l0); hfsplit(yA1, h1, l1);
        fh[ks][0] = pk(h0, h1); fl[ks][0] = pk(l0, l1);
        hfsplit(yB0, h0, l0); hfsplit(yB1, h1, l1);
        fh[ks][1] = pk(h0, h1); fl[ks][1] = pk(l0, l1);
        hfsplit(yA2, h0, l0); hfsplit(yA3, h1, l1);
        fh[ks][2] = pk(h0, h1); fl[ks][2] = pk(l0, l1);
        hfsplit(yB2, h0, l0); hfsplit(yB3, h1, l1);
        fh[ks][3] = pk(h0, h1); fl[ks][3] = pk(l0, l1);
    }
}

__global__ __launch_bounds__(THREADS, 1)
void EdgeModel_48636209660177_kernel(
    const float* __restrict__ src, const float* __restrict__ dst,
    const float* __restrict__ ea,
    const float* __restrict__ W1, const float* __restrict__ b1,
    const float* __restrict__ g1, const float* __restrict__ be1,
    const float* __restrict__ W2, const float* __restrict__ b2,
    const float* __restrict__ g2, const float* __restrict__ be2,
    const float* __restrict__ W3, const float* __restrict__ b3,
    float* __restrict__ out)
{
    extern __shared__ char smem[];
    const u32 smb = smem_u32(smem);
    const int tid = threadIdx.x, lane = tid & 31, warp = tid >> 5;
    float* lnp = (float*)(smem + LNP);

    // ---- one-time: weights -> transposed fp16; LN params -> smem ----
    for (int i = tid; i < 96 * 64; i += THREADS) {
        int k = i >> 6, n = i & 63;
        *(u16*)(smem + W1H + (n * 104 + k) * 2) = hf(__ldg(&W1[i]));
    }
    for (int i = tid; i < 160 * 64; i += THREADS) {
        int k = i >> 6, n = i & 63;
        *(u16*)(smem + W2H + (n * 168 + k) * 2) = hf(__ldg(&W2[i]));
    }
    for (int i = tid; i < 64 * 32; i += THREADS) {
        int k = i >> 5, n = i & 31;
        *(u16*)(smem + W3H + (n * 72 + k) * 2) = hf(__ldg(&W3[i]));
    }
    for (int i = tid; i < 64; i += THREADS) {
        lnp[i] = b1[i]; lnp[64 + i] = g1[i]; lnp[128 + i] = be1[i];
        lnp[192 + i] = b2[i]; lnp[256 + i] = g2[i]; lnp[320 + i] = be2[i];
    }
    for (int i = tid; i < 32; i += THREADS) lnp[384 + i] = b3[i];
    __syncthreads();

    const int e0 = warp * 16;                 // this warp's 16 edge rows (fixed)
    const int tg = lane & 3, gid = lane >> 2;
    const int arow = lane & 15, asel = lane >> 4;       // A ldmatrix addressing
    const int brow = ((lane >> 4) << 3) + (lane & 7);   // B pair-x4 addressing
    const int boff = ((lane >> 3) & 1) * 16;

    for (int tile = blockIdx.x; tile < NTILES; tile += GRID) {
        const int eb = tile * TILE_E;
        __syncwarp();   // prior tile's x0H ldmatrix reads complete before overwrite

        // ---- stage own 16 edges of x0 hi into smem ([e][k] stride 104) ----
        for (int i = lane; i < 16 * 24; i += 32) {
            int el = i / 24, s = i % 24;
            int ge = eb + e0 + el;
            const float* g = (s < 8) ? src : (s < 16) ? dst : ea;
            int seg = s & 7;
            float4 v = make_float4(0.f, 0.f, 0.f, 0.f);
            if (ge < E_TOTAL) v = *(const float4*)(g + (size_t)ge * 32 + seg * 4);
            int col = (s >> 3) * 32 + seg * 4;
            *(uint2*)(smem + X0H + ((e0 + el) * 104 + col) * 2) =
                make_uint2(pk(hf(v.x), hf(v.y)), pk(hf(v.z), hf(v.w)));
        }

        // ---- x0 lo-split A-fragments straight into registers (L2-hot reload) ----
        u32 x0lo[6][4];
        {
            int r0 = eb + e0 + gid, r1 = r0 + 8;
#pragma unroll
            for (int ks = 0; ks < 6; ks++) {
                int k0 = ks * 16 + 2 * tg;
                x0lo[ks][0] = lo2(x0f2(src, dst, ea, r0, k0));
                x0lo[ks][1] = lo2(x0f2(src, dst, ea, r1, k0));
                x0lo[ks][2] = lo2(x0f2(src, dst, ea, r0, k0 + 8));
                x0lo[ks][3] = lo2(x0f2(src, dst, ea, r1, k0 + 8));
            }
        }
        __syncwarp();

        float c[8][4];
        u32 fh[4][4], fl[4][4];

        // ================= layer 1: x0[96] @ W1 -> 64 =================
#pragma unroll
        for (int j = 0; j < 8; j++)
#pragma unroll
            for (int q = 0; q < 4; q++) c[j][q] = 0.f;
#pragma unroll
        for (int ks = 0; ks < 6; ks++) {
            int k0 = ks * 16;
            u32 aH[4];
            ldmx4(aH, smb + X0H + ((e0 + arow) * 104 + k0 + asel * 8) * 2);
#pragma unroll
            for (int jp = 0; jp < 8; jp += 2) {
                u32 addr = ((jp * 8 + brow) * 104 + k0) * 2 + boff;
                u32 bH[4];
                ldmx4(bH, smb + W1H + addr);
                mmafp(c[jp], aH, bH[0], bH[1]);
                mmafp(c[jp], x0lo[ks], bH[0], bH[1]);
                mmafp(c[jp + 1], aH, bH[2], bH[3]);
                mmafp(c[jp + 1], x0lo[ks], bH[2], bH[3]);
            }
        }
        ln_frag(c, lnp, lnp + 64, lnp + 128, fh, fl, lane);

        // ================= layer 2: [h1(64), x0(96)] @ W2 -> 64 =================
#pragma unroll
        for (int j = 0; j < 8; j++)
#pragma unroll
            for (int q = 0; q < 4; q++) c[j][q] = 0.f;
#pragma unroll
        for (int ks = 0; ks < 10; ks++) {
            int kb = ks * 16;
            u32 aHbuf[4];
            const u32 *pH, *pL;
            if (ks < 4) {
                pH = fh[ks]; pL = fl[ks];
            } else {
                ldmx4(aHbuf, smb + X0H + ((e0 + arow) * 104 + (kb - 64) + asel * 8) * 2);
                pH = aHbuf; pL = x0lo[ks - 4];
            }
#pragma unroll
            for (int jp = 0; jp < 8; jp += 2) {
                u32 addr = ((jp * 8 + brow) * 168 + kb) * 2 + boff;
                u32 bH[4];
                ldmx4(bH, smb + W2H + addr);
                mmafp(c[jp], pH, bH[0], bH[1]);
                mmafp(c[jp], pL, bH[0], bH[1]);
                mmafp(c[jp + 1], pH, bH[2], bH[3]);
                mmafp(c[jp + 1], pL, bH[2], bH[3]);
            }
        }
        ln_frag(c, lnp + 192, lnp + 256, lnp + 320, fh, fl, lane);

        // ================= layer 3: h2[64] @ W3 -> 32, + b3 -> gmem =================
        {
            float c3[4][4];
#pragma unroll
            for (int j = 0; j < 4; j++)
#pragma unroll
                for (int q = 0; q < 4; q++) c3[j][q] = 0.f;
#pragma unroll
            for (int ks = 0; ks < 4; ks++) {
                int k0 = ks * 16;
#pragma unroll
                for (int jp = 0; jp < 4; jp += 2) {
                    u32 addr = ((jp * 8 + brow) * 72 + k0) * 2 + boff;
                    u32 bH[4];
                    ldmx4(bH, smb + W3H + addr);
                    mmafp(c3[jp], fh[ks], bH[0], bH[1]);
                    mmafp(c3[jp], fl[ks], bH[0], bH[1]);
                    mmafp(c3[jp + 1], fh[ks], bH[2], bH[3]);
                    mmafp(c3[jp + 1], fl[ks], bH[2], bH[3]);
                }
            }
            int geA = eb + e0 + gid, geB = geA + 8;
#pragma unroll
            for (int j = 0; j < 4; j++) {
                int col = 8 * j + 2 * tg;
                float bb0 = lnp[384 + col], bb1 = lnp[384 + col + 1];
                if (geA < E_TOTAL)
                    *(float2*)(out + (size_t)geA * 32 + col) =
                        make_float2(c3[j][0] + bb0, c3[j][1] + bb1);
                if (geB < E_TOTAL)
                    *(float2*)(out + (size_t)geB * 32 + col) =
                        make_float2(c3[j][2] + bb0, c3[j][3] + bb1);
            }
        }
    }
}

extern "C" void kernel_launch(void* const* d_in, const int* in_sizes, int n_in,
                              void* d_out, int out_size) {
    (void)in_sizes; (void)n_in; (void)out_size;
    const float* src = (const float*)d_in[0];
    const float* dst = (const float*)d_in[1];
    const float* ea  = (const float*)d_in[2];
    const float* W1  = (const float*)d_in[3];
    const float* b1  = (const float*)d_in[4];
    const float* g1  = (const float*)d_in[5];
    const float* be1 = (const float*)d_in[6];
    const float* W2  = (const float*)d_in[7];
    const float* b2  = (const float*)d_in[8];
    const float* g2  = (const float*)d_in[9];
    const float* be2 = (const float*)d_in[10];
    const float* W3  = (const float*)d_in[11];
    const float* b3  = (const float*)d_in[12];
    float* out = (float*)d_out;

    cudaFuncSetAttribute(EdgeModel_48636209660177_kernel,
                         cudaFuncAttributeMaxDynamicSharedMemorySize, SMEM_TOTAL);
    EdgeModel_48636209660177_kernel<<<GRID, THREADS, SMEM_TOTAL>>>(
        src, dst, ea, W1, b1, g1, be1, W2, b2, g2, be2, W3, b3, out);
}

// round 15
// speedup vs baseline: 2.2670x; 1.1220x over previous
#include <cuda_runtime.h>
#include <cuda_fp16.h>

#define E_TOTAL 1000000
#define THREADS 512
#define TILE_E  256
#define NTILES  ((E_TOTAL + TILE_E - 1) / TILE_E)
#define GRID    152
#define LN_EPS  1e-5f

typedef unsigned int u32;
typedef unsigned short u16;

// ---- SMEM byte offsets ----
// weights transposed [n][k] fp16, padded strides (halves): W1 104, W2 168, W3 72
#define W1H 0
#define W2H 13312
#define W3H 34816
#define X0H 39424       // x0 hi, [256][104] fp16
#define X0L 92672       // x0 lo, [256][104] fp16
#define LNP 145920      // 416 floats: b1,g1,be1,b2,g2,be2 (64 each), b3 (32)
#define SMEM_TOTAL (145920 + 416*4)   // 147584

__device__ __forceinline__ u32 smem_u32(const void* p) {
    u32 a;
    asm("{ .reg .u64 t; cvta.to.shared.u64 t, %1; cvt.u32.u64 %0, t; }" : "=r"(a) : "l"(p));
    return a;
}
__device__ __forceinline__ void ldmx4(u32 r[4], u32 addr) {
    asm volatile("ldmatrix.sync.aligned.m8n8.x4.shared.b16 {%0,%1,%2,%3}, [%4];"
                 : "=r"(r[0]), "=r"(r[1]), "=r"(r[2]), "=r"(r[3]) : "r"(addr));
}
__device__ __forceinline__ void mmafp(float c[4], const u32 a[4], u32 b0, u32 b1) {
    asm volatile(
        "mma.sync.aligned.m16n8k16.row.col.f32.f16.f16.f32 "
        "{%0,%1,%2,%3}, {%4,%5,%6,%7}, {%8,%9}, {%0,%1,%2,%3};"
        : "+f"(c[0]), "+f"(c[1]), "+f"(c[2]), "+f"(c[3])
        : "r"(a[0]), "r"(a[1]), "r"(a[2]), "r"(a[3]), "r"(b0), "r"(b1));
}
__device__ __forceinline__ u32 h2u(__half2 h) { return *(u32*)&h; }
// packed split: (x,y) -> hi half2, lo half2 (lo = exact residual rounded)
__device__ __forceinline__ void hsplit2(float x, float y, u32 &hi, u32 &lo) {
    __half2 h = __floats2half2_rn(x, y);
    float2 b = __half22float2(h);
    __half2 l = __floats2half2_rn(x - b.x, y - b.y);
    hi = h2u(h); lo = h2u(l);
}
__device__ __forceinline__ u16 hf(float x) {
    __half hh = __float2half_rn(x);
    return __half_as_ushort(hh);
}

// relu -> LN(64) -> fp16 hi/lo A-fragments (4 k-steps) entirely in registers.
// Thread (tg,gid) owns rows gid/gid+8, cols 8j+2tg — exactly the mma fragment set.
__device__ __forceinline__ void ln_frag(
    const float c[8][4], const float* __restrict__ lnb, const float* __restrict__ lng,
    const float* __restrict__ lnbe, u32 fh[4][4], u32 fl[4][4], int lane)
{
    const int tg = lane & 3;
    float vA[16], vB[16], sA = 0.f, qA = 0.f, sB = 0.f, qB = 0.f;
#pragma unroll
    for (int j = 0; j < 8; j++) {
        int col = 8 * j + 2 * tg;
        float b0 = lnb[col], b1 = lnb[col + 1];
        float a0 = fmaxf(c[j][0] + b0, 0.f), a1 = fmaxf(c[j][1] + b1, 0.f);
        float d0 = fmaxf(c[j][2] + b0, 0.f), d1 = fmaxf(c[j][3] + b1, 0.f);
        vA[2 * j] = a0; vA[2 * j + 1] = a1;
        vB[2 * j] = d0; vB[2 * j + 1] = d1;
        sA += a0 + a1; qA += a0 * a0 + a1 * a1;
        sB += d0 + d1; qB += d0 * d0 + d1 * d1;
    }
#pragma unroll
    for (int m = 1; m < 4; m <<= 1) {
        sA += __shfl_xor_sync(0xffffffffu, sA, m);
        qA += __shfl_xor_sync(0xffffffffu, qA, m);
        sB += __shfl_xor_sync(0xffffffffu, sB, m);
        qB += __shfl_xor_sync(0xffffffffu, qB, m);
    }
    float mA = sA * (1.f / 64.f), mB = sB * (1.f / 64.f);
    float rA = rsqrtf(qA * (1.f / 64.f) - mA * mA + LN_EPS);
    float rB = rsqrtf(qB * (1.f / 64.f) - mB * mB + LN_EPS);
#pragma unroll
    for (int ks = 0; ks < 4; ks++) {
        int c0 = 16 * ks + 2 * tg, c1 = c0 + 8;
        float g0 = lng[c0], g1v = lng[c0 + 1], g2v = lng[c1], g3 = lng[c1 + 1];
        float p0 = lnbe[c0], p1 = lnbe[c0 + 1], p2 = lnbe[c1], p3 = lnbe[c1 + 1];
        float yA0 = (vA[4 * ks] - mA) * rA * g0 + p0;
        float yA1 = (vA[4 * ks + 1] - mA) * rA * g1v + p1;
        float yA2 = (vA[4 * ks + 2] - mA) * rA * g2v + p2;
        float yA3 = (vA[4 * ks + 3] - mA) * rA * g3 + p3;
        float yB0 = (vB[4 * ks] - mB) * rB * g0 + p0;
        float yB1 = (vB[4 * ks + 1] - mB) * rB * g1v + p1;
        float yB2 = (vB[4 * ks + 2] - mB) * rB * g2v + p2;
        float yB3 = (vB[4 * ks + 3] - mB) * rB * g3 + p3;
        hsplit2(yA0, yA1, fh[ks][0], fl[ks][0]);
        hsplit2(yB0, yB1, fh[ks][1], fl[ks][1]);
        hsplit2(yA2, yA3, fh[ks][2], fl[ks][2]);
        hsplit2(yB2, yB3, fh[ks][3], fl[ks][3]);
    }
}

__global__ __launch_bounds__(THREADS, 1)
void EdgeModel_48636209660177_kernel(
    const float* __restrict__ src, const float* __restrict__ dst,
    const float* __restrict__ ea,
    const float* __restrict__ W1, const float* __restrict__ b1,
    const float* __restrict__ g1, const float* __restrict__ be1,
    const float* __restrict__ W2, const float* __restrict__ b2,
    const float* __restrict__ g2, const float* __restrict__ be2,
    const float* __restrict__ W3, const float* __restrict__ b3,
    float* __restrict__ out)
{
    extern __shared__ char smem[];
    const u32 smb = smem_u32(smem);
    const int tid = threadIdx.x, lane = tid & 31, warp = tid >> 5;
    float* lnp = (float*)(smem + LNP);

    // ---- one-time: weights -> transposed fp16; LN params -> smem ----
    for (int i = tid; i < 96 * 64; i += THREADS) {
        int k = i >> 6, n = i & 63;
        *(u16*)(smem + W1H + (n * 104 + k) * 2) = hf(__ldg(&W1[i]));
    }
    for (int i = tid; i < 160 * 64; i += THREADS) {
        int k = i >> 6, n = i & 63;
        *(u16*)(smem + W2H + (n * 168 + k) * 2) = hf(__ldg(&W2[i]));
    }
    for (int i = tid; i < 64 * 32; i += THREADS) {
        int k = i >> 5, n = i & 31;
        *(u16*)(smem + W3H + (n * 72 + k) * 2) = hf(__ldg(&W3[i]));
    }
    for (int i = tid; i < 64; i += THREADS) {
        lnp[i] = b1[i]; lnp[64 + i] = g1[i]; lnp[128 + i] = be1[i];
        lnp[192 + i] = b2[i]; lnp[256 + i] = g2[i]; lnp[320 + i] = be2[i];
    }
    for (int i = tid; i < 32; i += THREADS) lnp[384 + i] = b3[i];
    __syncthreads();

    const int e0 = warp * 16;                 // this warp's 16 edge rows (fixed)
    const int tg = lane & 3, gid = lane >> 2;
    const int arow = lane & 15, asel = lane >> 4;       // A ldmatrix addressing
    const int brow = ((lane >> 4) << 3) + (lane & 7);   // B pair-x4 addressing
    const int boff = ((lane >> 3) & 1) * 16;

    for (int tile = blockIdx.x; tile < NTILES; tile += GRID) {
        const int eb = tile * TILE_E;
        __syncwarp();   // prior tile's x0 ldmatrix reads complete before overwrite

        // ---- stage own 16 edges of x0 hi+lo into smem ([e][k] stride 104) ----
        for (int i = lane; i < 16 * 24; i += 32) {
            int el = i / 24, s = i % 24;
            int ge = eb + e0 + el;
            const float* g = (s < 8) ? src : (s < 16) ? dst : ea;
            int seg = s & 7;
            float4 v = make_float4(0.f, 0.f, 0.f, 0.f);
            if (ge < E_TOTAL) v = *(const float4*)(g + (size_t)ge * 32 + seg * 4);
            int col = (s >> 3) * 32 + seg * 4;
            u32 h0, l0, h1, l1;
            hsplit2(v.x, v.y, h0, l0);
            hsplit2(v.z, v.w, h1, l1);
            int off = ((e0 + el) * 104 + col) * 2;
            *(uint2*)(smem + X0H + off) = make_uint2(h0, h1);
            *(uint2*)(smem + X0L + off) = make_uint2(l0, l1);
        }
        __syncwarp();

        float c[8][4];
        u32 fh[4][4], fl[4][4];

        // ================= layer 1: x0[96] @ W1 -> 64 =================
#pragma unroll
        for (int j = 0; j < 8; j++)
#pragma unroll
            for (int q = 0; q < 4; q++) c[j][q] = 0.f;
#pragma unroll
        for (int ks = 0; ks < 6; ks++) {
            int k0 = ks * 16;
            u32 aH[4], aL[4];
            u32 offA = ((e0 + arow) * 104 + k0 + asel * 8) * 2;
            ldmx4(aH, smb + X0H + offA);
            ldmx4(aL, smb + X0L + offA);
#pragma unroll
            for (int jp = 0; jp < 8; jp += 2) {
                u32 addr = ((jp * 8 + brow) * 104 + k0) * 2 + boff;
                u32 bH[4];
                ldmx4(bH, smb + W1H + addr);
                mmafp(c[jp], aH, bH[0], bH[1]);
                mmafp(c[jp], aL, bH[0], bH[1]);
                mmafp(c[jp + 1], aH, bH[2], bH[3]);
                mmafp(c[jp + 1], aL, bH[2], bH[3]);
            }
        }
        ln_frag(c, lnp, lnp + 64, lnp + 128, fh, fl, lane);

        // ================= layer 2: [h1(64), x0(96)] @ W2 -> 64 =================
#pragma unroll
        for (int j = 0; j < 8; j++)
#pragma unroll
            for (int q = 0; q < 4; q++) c[j][q] = 0.f;
#pragma unroll
        for (int ks = 0; ks < 10; ks++) {
            int kb = ks * 16;
            u32 aHbuf[4], aLbuf[4];
            const u32 *pH, *pL;
            if (ks < 4) {
                pH = fh[ks]; pL = fl[ks];
            } else {
                u32 offA = ((e0 + arow) * 104 + (kb - 64) + asel * 8) * 2;
                ldmx4(aHbuf, smb + X0H + offA);
                ldmx4(aLbuf, smb + X0L + offA);
                pH = aHbuf; pL = aLbuf;
            }
#pragma unroll
            for (int jp = 0; jp < 8; jp += 2) {
                u32 addr = ((jp * 8 + brow) * 168 + kb) * 2 + boff;
                u32 bH[4];
                ldmx4(bH, smb + W2H + addr);
                mmafp(c[jp], pH, bH[0], bH[1]);
                mmafp(c[jp], pL, bH[0], bH[1]);
                mmafp(c[jp + 1], pH, bH[2], bH[3]);
                mmafp(c[jp + 1], pL, bH[2], bH[3]);
            }
        }
        ln_frag(c, lnp + 192, lnp + 256, lnp + 320, fh, fl, lane);

        // ================= layer 3: h2[64] @ W3 -> 32, + b3 -> gmem =================
        {
            float c3[4][4];
#pragma unroll
            for (int j = 0; j < 4; j++)
#pragma unroll
                for (int q = 0; q < 4; q++) c3[j][q] = 0.f;
#pragma unroll
            for (int ks = 0; ks < 4; ks++) {
                int k0 = ks * 16;
#pragma unroll
                for (int jp = 0; jp < 4; jp += 2) {
                    u32 addr = ((jp * 8 + brow) * 72 + k0) * 2 + boff;
                    u32 bH[4];
                    ldmx4(bH, smb + W3H + addr);
                    mmafp(c3[jp], fh[ks], bH[0], bH[1]);
                    mmafp(c3[jp], fl[ks], bH[0], bH[1]);
                    mmafp(c3[jp + 1], fh[ks], bH[2], bH[3]);
                    mmafp(c3[jp + 1], fl[ks], bH[2], bH[3]);
                }
            }
            int geA = eb + e0 + gid, geB = geA + 8;
#pragma unroll
            for (int j = 0; j < 4; j++) {
                int col = 8 * j + 2 * tg;
                float bb0 = lnp[384 + col], bb1 = lnp[384 + col + 1];
                if (geA < E_TOTAL)
                    *(float2*)(out + (size_t)geA * 32 + col) =
                        make_float2(c3[j][0] + bb0, c3[j][1] + bb1);
                if (geB < E_TOTAL)
                    *(float2*)(out + (size_t)geB * 32 + col) =
                        make_float2(c3[j][2] + bb0, c3[j][3] + bb1);
            }
        }
    }
}

extern "C" void kernel_launch(void* const* d_in, const int* in_sizes, int n_in,
                              void* d_out, int out_size) {
    (void)in_sizes; (void)n_in; (void)out_size;
    const float* src = (const float*)d_in[0];
    const float* dst = (const float*)d_in[1];
    const float* ea  = (const float*)d_in[2];
    const float* W1  = (const float*)d_in[3];
    const float* b1  = (const float*)d_in[4];
    const float* g1  = (const float*)d_in[5];
    const float* be1 = (const float*)d_in[6];
    const float* W2  = (const float*)d_in[7];
    const float* b2  = (const float*)d_in[8];
    const float* g2  = (const float*)d_in[9];
    const float* be2 = (const float*)d_in[10];
    const float* W3  = (const float*)d_in[11];
    const float* b3  = (const float*)d_in[12];
    float* out = (float*)d_out;

    cudaFuncSetAttribute(EdgeModel_48636209660177_kernel,
                         cudaFuncAttributeMaxDynamicSharedMemorySize, SMEM_TOTAL);
    EdgeModel_48636209660177_kernel<<<GRID, THREADS, SMEM_TOTAL>>>(
        src, dst, ea, W1, b1, g1, be1, W2, b2, g2, be2, W3, b3, out);
}

// round 16
// speedup vs baseline: 3.1910x; 1.4076x over previous
#include <cuda_runtime.h>
#include <cuda_fp16.h>

#define E_TOTAL 1000000
#define THREADS 512
#define TILE_E  256
#define NTILES  ((E_TOTAL + TILE_E - 1) / TILE_E)
#define GRID    152
#define LN_EPS  1e-5f

typedef unsigned int u32;
typedef unsigned short u16;

// ---- SMEM byte offsets ----
// weights transposed [n][k] fp16, padded strides (halves): W1 104, W2 168, W3 72
#define W1H 0
#define W2H 13312
#define W3H 34816
#define X0H 39424       // x0 hi, [256][104] fp16
#define LNP 92672       // 416 floats: b1,g1,be1,b2,g2,be2 (64 each), b3 (32)
#define SMEM_TOTAL (92672 + 416*4)   // 94336

__device__ __forceinline__ u32 smem_u32(const void* p) {
    u32 a;
    asm("{ .reg .u64 t; cvta.to.shared.u64 t, %1; cvt.u32.u64 %0, t; }" : "=r"(a) : "l"(p));
    return a;
}
__device__ __forceinline__ void ldmx4(u32 r[4], u32 addr) {
    asm volatile("ldmatrix.sync.aligned.m8n8.x4.shared.b16 {%0,%1,%2,%3}, [%4];"
                 : "=r"(r[0]), "=r"(r[1]), "=r"(r[2]), "=r"(r[3]) : "r"(addr));
}
__device__ __forceinline__ void mmafp(float c[4], const u32 a[4], u32 b0, u32 b1) {
    asm volatile(
        "mma.sync.aligned.m16n8k16.row.col.f32.f16.f16.f32 "
        "{%0,%1,%2,%3}, {%4,%5,%6,%7}, {%8,%9}, {%0,%1,%2,%3};"
        : "+f"(c[0]), "+f"(c[1]), "+f"(c[2]), "+f"(c[3])
        : "r"(a[0]), "r"(a[1]), "r"(a[2]), "r"(a[3]), "r"(b0), "r"(b1));
}
__device__ __forceinline__ u32 h2u(__half2 h) { return *(u32*)&h; }
__device__ __forceinline__ u32 hi2(float x, float y) {
    return h2u(__floats2half2_rn(x, y));
}
// packed split: (x,y) -> hi half2, lo half2 (lo = exact residual rounded)
__device__ __forceinline__ void hsplit2(float x, float y, u32 &hi, u32 &lo) {
    __half2 h = __floats2half2_rn(x, y);
    float2 b = __half22float2(h);
    __half2 l = __floats2half2_rn(x - b.x, y - b.y);
    hi = h2u(h); lo = h2u(l);
}
__device__ __forceinline__ u16 hf(float x) {
    __half hh = __float2half_rn(x);
    return __half_as_ushort(hh);
}

// relu -> LN(64) -> fp16 hi/lo A-fragments (4 k-steps) entirely in registers.
// Thread (tg,gid) owns rows gid/gid+8, cols 8j+2tg — exactly the mma fragment set.
__device__ __forceinline__ void ln_frag(
    const float c[8][4], const float* __restrict__ lnb, const float* __restrict__ lng,
    const float* __restrict__ lnbe, u32 fh[4][4], u32 fl[4][4], int lane)
{
    const int tg = lane & 3;
    float vA[16], vB[16], sA = 0.f, qA = 0.f, sB = 0.f, qB = 0.f;
#pragma unroll
    for (int j = 0; j < 8; j++) {
        int col = 8 * j + 2 * tg;
        float b0 = lnb[col], b1 = lnb[col + 1];
        float a0 = fmaxf(c[j][0] + b0, 0.f), a1 = fmaxf(c[j][1] + b1, 0.f);
        float d0 = fmaxf(c[j][2] + b0, 0.f), d1 = fmaxf(c[j][3] + b1, 0.f);
        vA[2 * j] = a0; vA[2 * j + 1] = a1;
        vB[2 * j] = d0; vB[2 * j + 1] = d1;
        sA += a0 + a1; qA += a0 * a0 + a1 * a1;
        sB += d0 + d1; qB += d0 * d0 + d1 * d1;
    }
#pragma unroll
    for (int m = 1; m < 4; m <<= 1) {
        sA += __shfl_xor_sync(0xffffffffu, sA, m);
        qA += __shfl_xor_sync(0xffffffffu, qA, m);
        sB += __shfl_xor_sync(0xffffffffu, sB, m);
        qB += __shfl_xor_sync(0xffffffffu, qB, m);
    }
    float mA = sA * (1.f / 64.f), mB = sB * (1.f / 64.f);
    float rA = rsqrtf(qA * (1.f / 64.f) - mA * mA + LN_EPS);
    float rB = rsqrtf(qB * (1.f / 64.f) - mB * mB + LN_EPS);
#pragma unroll
    for (int ks = 0; ks < 4; ks++) {
        int c0 = 16 * ks + 2 * tg, c1 = c0 + 8;
        float g0 = lng[c0], g1v = lng[c0 + 1], g2v = lng[c1], g3 = lng[c1 + 1];
        float p0 = lnbe[c0], p1 = lnbe[c0 + 1], p2 = lnbe[c1], p3 = lnbe[c1 + 1];
        float yA0 = (vA[4 * ks] - mA) * rA * g0 + p0;
        float yA1 = (vA[4 * ks + 1] - mA) * rA * g1v + p1;
        float yA2 = (vA[4 * ks + 2] - mA) * rA * g2v + p2;
        float yA3 = (vA[4 * ks + 3] - mA) * rA * g3 + p3;
        float yB0 = (vB[4 * ks] - mB) * rB * g0 + p0;
        float yB1 = (vB[4 * ks + 1] - mB) * rB * g1v + p1;
        float yB2 = (vB[4 * ks + 2] - mB) * rB * g2v + p2;
        float yB3 = (vB[4 * ks + 3] - mB) * rB * g3 + p3;
        hsplit2(yA0, yA1, fh[ks][0], fl[ks][0]);
        hsplit2(yB0, yB1, fh[ks][1], fl[ks][1]);
        hsplit2(yA2, yA3, fh[ks][2], fl[ks][2]);
        hsplit2(yB2, yB3, fh[ks][3], fl[ks][3]);
    }
}

__global__ __launch_bounds__(THREADS, 1)
void EdgeModel_48636209660177_kernel(
    const float* __restrict__ src, const float* __restrict__ dst,
    const float* __restrict__ ea,
    const float* __restrict__ W1, const float* __restrict__ b1,
    const float* __restrict__ g1, const float* __restrict__ be1,
    const float* __restrict__ W2, const float* __restrict__ b2,
    const float* __restrict__ g2, const float* __restrict__ be2,
    const float* __restrict__ W3, const float* __restrict__ b3,
    float* __restrict__ out)
{
    extern __shared__ char smem[];
    const u32 smb = smem_u32(smem);
    const int tid = threadIdx.x, lane = tid & 31, warp = tid >> 5;
    float* lnp = (float*)(smem + LNP);

    // ---- one-time: weights -> transposed fp16; LN params -> smem ----
    for (int i = tid; i < 96 * 64; i += THREADS) {
        int k = i >> 6, n = i & 63;
        *(u16*)(smem + W1H + (n * 104 + k) * 2) = hf(__ldg(&W1[i]));
    }
    for (int i = tid; i < 160 * 64; i += THREADS) {
        int k = i >> 6, n = i & 63;
        *(u16*)(smem + W2H + (n * 168 + k) * 2) = hf(__ldg(&W2[i]));
    }
    for (int i = tid; i < 64 * 32; i += THREADS) {
        int k = i >> 5, n = i & 31;
        *(u16*)(smem + W3H + (n * 72 + k) * 2) = hf(__ldg(&W3[i]));
    }
    for (int i = tid; i < 64; i += THREADS) {
        lnp[i] = b1[i]; lnp[64 + i] = g1[i]; lnp[128 + i] = be1[i];
        lnp[192 + i] = b2[i]; lnp[256 + i] = g2[i]; lnp[320 + i] = be2[i];
    }
    for (int i = tid; i < 32; i += THREADS) lnp[384 + i] = b3[i];
    __syncthreads();

    const int e0 = warp * 16;                 // this warp's 16 edge rows (fixed)
    const int tg = lane & 3, gid = lane >> 2;
    const int arow = lane & 15, asel = lane >> 4;       // A ldmatrix addressing
    const int brow = ((lane >> 4) << 3) + (lane & 7);   // B pair-x4 addressing
    const int boff = ((lane >> 3) & 1) * 16;
    const int sel = lane >> 3, sseg = lane & 7;         // staging: el-sub, seg (no div)

    for (int tile = blockIdx.x; tile < NTILES; tile += GRID) {
        const int eb = tile * TILE_E;
        __syncwarp();   // prior tile's x0 ldmatrix reads complete before overwrite

        // ---- stage own 16 edges of x0 hi into smem ([e][k] stride 104) ----
#pragma unroll
        for (int t = 0; t < 3; t++) {
            const float* g = (t == 0) ? src : (t == 1) ? dst : ea;
#pragma unroll
            for (int it = 0; it < 4; it++) {
                int el = it * 4 + sel;          // 0..15
                int ge = eb + e0 + el;
                float4 v = make_float4(0.f, 0.f, 0.f, 0.f);
                if (ge < E_TOTAL) v = *(const float4*)(g + (size_t)ge * 32 + sseg * 4);
                int col = t * 32 + sseg * 4;
                *(uint2*)(smem + X0H + ((e0 + el) * 104 + col) * 2) =
                    make_uint2(hi2(v.x, v.y), hi2(v.z, v.w));
            }
        }
        __syncwarp();

        float c[8][4];
        u32 fh[4][4], fl[4][4];

        // ================= layer 1: x0[96] @ W1 -> 64 (1-term activations) =====
#pragma unroll
        for (int j = 0; j < 8; j++)
#pragma unroll
            for (int q = 0; q < 4; q++) c[j][q] = 0.f;
#pragma unroll
        for (int ks = 0; ks < 6; ks++) {
            int k0 = ks * 16;
            u32 aH[4];
            ldmx4(aH, smb + X0H + ((e0 + arow) * 104 + k0 + asel * 8) * 2);
#pragma unroll
            for (int jp = 0; jp < 8; jp += 2) {
                u32 addr = ((jp * 8 + brow) * 104 + k0) * 2 + boff;
                u32 bH[4];
                ldmx4(bH, smb + W1H + addr);
                mmafp(c[jp], aH, bH[0], bH[1]);
                mmafp(c[jp + 1], aH, bH[2], bH[3]);
            }
        }
        ln_frag(c, lnp, lnp + 64, lnp + 128, fh, fl, lane);

        // ================= layer 2: [h1(64), x0(96)] @ W2 -> 64 =================
#pragma unroll
        for (int j = 0; j < 8; j++)
#pragma unroll
            for (int q = 0; q < 4; q++) c[j][q] = 0.f;
        // h part (2-term, fragments already in registers)
#pragma unroll
        for (int ks = 0; ks < 4; ks++) {
            int kb = ks * 16;
#pragma unroll
            for (int jp = 0; jp < 8; jp += 2) {
                u32 addr = ((jp * 8 + brow) * 168 + kb) * 2 + boff;
                u32 bH[4];
                ldmx4(bH, smb + W2H + addr);
                mmafp(c[jp], fh[ks], bH[0], bH[1]);
                mmafp(c[jp], fl[ks], bH[0], bH[1]);
                mmafp(c[jp + 1], fh[ks], bH[2], bH[3]);
                mmafp(c[jp + 1], fl[ks], bH[2], bH[3]);
            }
        }
        // x0 part (1-term activations)
#pragma unroll
        for (int ks = 4; ks < 10; ks++) {
            int kb = ks * 16;
            u32 aH[4];
            ldmx4(aH, smb + X0H + ((e0 + arow) * 104 + (kb - 64) + asel * 8) * 2);
#pragma unroll
            for (int jp = 0; jp < 8; jp += 2) {
                u32 addr = ((jp * 8 + brow) * 168 + kb) * 2 + boff;
                u32 bH[4];
                ldmx4(bH, smb + W2H + addr);
                mmafp(c[jp], aH, bH[0], bH[1]);
                mmafp(c[jp + 1], aH, bH[2], bH[3]);
            }
        }
        ln_frag(c, lnp + 192, lnp + 256, lnp + 320, fh, fl, lane);

        // ================= layer 3: h2[64] @ W3 -> 32 (2-term), + b3 -> gmem ====
        {
            float c3[4][4];
#pragma unroll
            for (int j = 0; j < 4; j++)
#pragma unroll
                for (int q = 0; q < 4; q++) c3[j][q] = 0.f;
#pragma unroll
            for (int ks = 0; ks < 4; ks++) {
                int k0 = ks * 16;
#pragma unroll
                for (int jp = 0; jp < 4; jp += 2) {
                    u32 addr = ((jp * 8 + brow) * 72 + k0) * 2 + boff;
                    u32 bH[4];
                    ldmx4(bH, smb + W3H + addr);
                    mmafp(c3[jp], fh[ks], bH[0], bH[1]);
                    mmafp(c3[jp], fl[ks], bH[0], bH[1]);
                    mmafp(c3[jp + 1], fh[ks], bH[2], bH[3]);
                    mmafp(c3[jp + 1], fl[ks], bH[2], bH[3]);
                }
            }
            int geA = eb + e0 + gid, geB = geA + 8;
#pragma unroll
            for (int j = 0; j < 4; j++) {
                int col = 8 * j + 2 * tg;
                float bb0 = lnp[384 + col], bb1 = lnp[384 + col + 1];
                if (geA < E_TOTAL)
                    *(float2*)(out + (size_t)geA * 32 + col) =
                        make_float2(c3[j][0] + bb0, c3[j][1] + bb1);
                if (geB < E_TOTAL)
                    *(float2*)(out + (size_t)geB * 32 + col) =
                        make_float2(c3[j][2] + bb0, c3[j][3] + bb1);
            }
        }
    }
}

extern "C" void kernel_launch(void* const* d_in, const int* in_sizes, int n_in,
                              void* d_out, int out_size) {
    (void)in_sizes; (void)n_in; (void)out_size;
    const float* src = (const float*)d_in[0];
    const float* dst = (const float*)d_in[1];
    const float* ea  = (const float*)d_in[2];
    const float* W1  = (const float*)d_in[3];
    const float* b1  = (const float*)d_in[4];
    const float* g1  = (const float*)d_in[5];
    const float* be1 = (const float*)d_in[6];
    const float* W2  = (const float*)d_in[7];
    const float* b2  = (const float*)d_in[8];
    const float* g2  = (const float*)d_in[9];
    const float* be2 = (const float*)d_in[10];
    const float* W3  = (const float*)d_in[11];
    const float* b3  = (const float*)d_in[12];
    float* out = (float*)d_out;

    cudaFuncSetAttribute(EdgeModel_48636209660177_kernel,
                         cudaFuncAttributeMaxDynamicSharedMemorySize, SMEM_TOTAL);
    EdgeModel_48636209660177_kernel<<<GRID, THREADS, SMEM_TOTAL>>>(
        src, dst, ea, W1, b1, g1, be1, W2, b2, g2, be2, W3, b3, out);
}

// round 17
// speedup vs baseline: 3.2243x; 1.0104x over previous
#include <cuda_runtime.h>
#include <cuda_fp16.h>

#define E_TOTAL 1000000
#define THREADS 512
#define TILE_E  256
#define NTILES  ((E_TOTAL + TILE_E - 1) / TILE_E)
#define GRID    152
#define LN_EPS  1e-5f

typedef unsigned int u32;
typedef unsigned short u16;

// ---- SMEM byte offsets ----
// weights transposed [n][k] fp16, padded strides (halves): W1 104, W2 168, W3 72
#define W1H 0
#define W2H 13312
#define W3H 34816
#define X0H 39424       // x0 hi, [256][104] fp16
#define LNP 92672       // 416 floats: b1,g1,be1,b2,g2,be2 (64 each), b3 (32)
#define OUTS 94336      // per-warp out tiles: 16 warps x [16][36] floats (2304 B each)
#define SMEM_TOTAL (94336 + 16*2304)   // 131200

__device__ __forceinline__ u32 smem_u32(const void* p) {
    u32 a;
    asm("{ .reg .u64 t; cvta.to.shared.u64 t, %1; cvt.u32.u64 %0, t; }" : "=r"(a) : "l"(p));
    return a;
}
__device__ __forceinline__ void ldmx4(u32 r[4], u32 addr) {
    asm volatile("ldmatrix.sync.aligned.m8n8.x4.shared.b16 {%0,%1,%2,%3}, [%4];"
                 : "=r"(r[0]), "=r"(r[1]), "=r"(r[2]), "=r"(r[3]) : "r"(addr));
}
__device__ __forceinline__ void mmafp(float c[4], const u32 a[4], u32 b0, u32 b1) {
    asm volatile(
        "mma.sync.aligned.m16n8k16.row.col.f32.f16.f16.f32 "
        "{%0,%1,%2,%3}, {%4,%5,%6,%7}, {%8,%9}, {%0,%1,%2,%3};"
        : "+f"(c[0]), "+f"(c[1]), "+f"(c[2]), "+f"(c[3])
        : "r"(a[0]), "r"(a[1]), "r"(a[2]), "r"(a[3]), "r"(b0), "r"(b1));
}
__device__ __forceinline__ u32 h2u(__half2 h) { return *(u32*)&h; }
__device__ __forceinline__ u32 hi2(float x, float y) {
    return h2u(__floats2half2_rn(x, y));
}
// packed split: (x,y) -> hi half2, lo half2 (lo = exact residual rounded)
__device__ __forceinline__ void hsplit2(float x, float y, u32 &hi, u32 &lo) {
    __half2 h = __floats2half2_rn(x, y);
    float2 b = __half22float2(h);
    __half2 l = __floats2half2_rn(x - b.x, y - b.y);
    hi = h2u(h); lo = h2u(l);
}
__device__ __forceinline__ u16 hf(float x) {
    __half hh = __float2half_rn(x);
    return __half_as_ushort(hh);
}

// relu -> LN(64) -> fp16 hi/lo A-fragments (4 k-steps) entirely in registers.
// Thread (tg,gid) owns rows gid/gid+8, cols 8j+2tg — exactly the mma fragment set.
__device__ __forceinline__ void ln_frag(
    const float c[8][4], const float* __restrict__ lnb, const float* __restrict__ lng,
    const float* __restrict__ lnbe, u32 fh[4][4], u32 fl[4][4], int lane)
{
    const int tg = lane & 3;
    float vA[16], vB[16], sA = 0.f, qA = 0.f, sB = 0.f, qB = 0.f;
#pragma unroll
    for (int j = 0; j < 8; j++) {
        int col = 8 * j + 2 * tg;
        float b0 = lnb[col], b1 = lnb[col + 1];
        float a0 = fmaxf(c[j][0] + b0, 0.f), a1 = fmaxf(c[j][1] + b1, 0.f);
        float d0 = fmaxf(c[j][2] + b0, 0.f), d1 = fmaxf(c[j][3] + b1, 0.f);
        vA[2 * j] = a0; vA[2 * j + 1] = a1;
        vB[2 * j] = d0; vB[2 * j + 1] = d1;
        sA += a0 + a1; qA += a0 * a0 + a1 * a1;
        sB += d0 + d1; qB += d0 * d0 + d1 * d1;
    }
#pragma unroll
    for (int m = 1; m < 4; m <<= 1) {
        sA += __shfl_xor_sync(0xffffffffu, sA, m);
        qA += __shfl_xor_sync(0xffffffffu, qA, m);
        sB += __shfl_xor_sync(0xffffffffu, sB, m);
        qB += __shfl_xor_sync(0xffffffffu, qB, m);
    }
    float mA = sA * (1.f / 64.f), mB = sB * (1.f / 64.f);
    float rA = rsqrtf(qA * (1.f / 64.f) - mA * mA + LN_EPS);
    float rB = rsqrtf(qB * (1.f / 64.f) - mB * mB + LN_EPS);
#pragma unroll
    for (int ks = 0; ks < 4; ks++) {
        int c0 = 16 * ks + 2 * tg, c1 = c0 + 8;
        float g0 = lng[c0], g1v = lng[c0 + 1], g2v = lng[c1], g3 = lng[c1 + 1];
        float p0 = lnbe[c0], p1 = lnbe[c0 + 1], p2 = lnbe[c1], p3 = lnbe[c1 + 1];
        float yA0 = (vA[4 * ks] - mA) * rA * g0 + p0;
        float yA1 = (vA[4 * ks + 1] - mA) * rA * g1v + p1;
        float yA2 = (vA[4 * ks + 2] - mA) * rA * g2v + p2;
        float yA3 = (vA[4 * ks + 3] - mA) * rA * g3 + p3;
        float yB0 = (vB[4 * ks] - mB) * rB * g0 + p0;
        float yB1 = (vB[4 * ks + 1] - mB) * rB * g1v + p1;
        float yB2 = (vB[4 * ks + 2] - mB) * rB * g2v + p2;
        float yB3 = (vB[4 * ks + 3] - mB) * rB * g3 + p3;
        hsplit2(yA0, yA1, fh[ks][0], fl[ks][0]);
        hsplit2(yB0, yB1, fh[ks][1], fl[ks][1]);
        hsplit2(yA2, yA3, fh[ks][2], fl[ks][2]);
        hsplit2(yB2, yB3, fh[ks][3], fl[ks][3]);
    }
}

__global__ __launch_bounds__(THREADS, 1)
void EdgeModel_48636209660177_kernel(
    const float* __restrict__ src, const float* __restrict__ dst,
    const float* __restrict__ ea,
    const float* __restrict__ W1, const float* __restrict__ b1,
    const float* __restrict__ g1, const float* __restrict__ be1,
    const float* __restrict__ W2, const float* __restrict__ b2,
    const float* __restrict__ g2, const float* __restrict__ be2,
    const float* __restrict__ W3, const float* __restrict__ b3,
    float* __restrict__ out)
{
    extern __shared__ char smem[];
    const u32 smb = smem_u32(smem);
    const int tid = threadIdx.x, lane = tid & 31, warp = tid >> 5;
    float* lnp = (float*)(smem + LNP);

    // ---- one-time: weights -> transposed fp16; LN params -> smem ----
    for (int i = tid; i < 96 * 64; i += THREADS) {
        int k = i >> 6, n = i & 63;
        *(u16*)(smem + W1H + (n * 104 + k) * 2) = hf(__ldg(&W1[i]));
    }
    for (int i = tid; i < 160 * 64; i += THREADS) {
        int k = i >> 6, n = i & 63;
        *(u16*)(smem + W2H + (n * 168 + k) * 2) = hf(__ldg(&W2[i]));
    }
    for (int i = tid; i < 64 * 32; i += THREADS) {
        int k = i >> 5, n = i & 31;
        *(u16*)(smem + W3H + (n * 72 + k) * 2) = hf(__ldg(&W3[i]));
    }
    for (int i = tid; i < 64; i += THREADS) {
        lnp[i] = b1[i]; lnp[64 + i] = g1[i]; lnp[128 + i] = be1[i];
        lnp[192 + i] = b2[i]; lnp[256 + i] = g2[i]; lnp[320 + i] = be2[i];
    }
    for (int i = tid; i < 32; i += THREADS) lnp[384 + i] = b3[i];
    __syncthreads();

    const int e0 = warp * 16;                 // this warp's 16 edge rows (fixed)
    const int tg = lane & 3, gid = lane >> 2;
    const int arow = lane & 15, asel = lane >> 4;       // A ldmatrix addressing
    const int brow = ((lane >> 4) << 3) + (lane & 7);   // B pair-x4 addressing
    const int boff = ((lane >> 3) & 1) * 16;
    const int sel = lane >> 3, sseg = lane & 7;         // staging: el-sub, seg (no div)
    float* ob = (float*)(smem + OUTS) + warp * (16 * 36);   // out stage [16][36]

    for (int tile = blockIdx.x; tile < NTILES; tile += GRID) {
        const int eb = tile * TILE_E;
        __syncwarp();   // prior tile's x0 ldmatrix reads complete before overwrite

        // ---- stage own 16 edges of x0 hi into smem ([e][k] stride 104) ----
#pragma unroll
        for (int t = 0; t < 3; t++) {
            const float* g = (t == 0) ? src : (t == 1) ? dst : ea;
#pragma unroll
            for (int it = 0; it < 4; it++) {
                int el = it * 4 + sel;          // 0..15
                int ge = eb + e0 + el;
                float4 v = make_float4(0.f, 0.f, 0.f, 0.f);
                if (ge < E_TOTAL) v = *(const float4*)(g + (size_t)ge * 32 + sseg * 4);
                int col = t * 32 + sseg * 4;
                *(uint2*)(smem + X0H + ((e0 + el) * 104 + col) * 2) =
                    make_uint2(hi2(v.x, v.y), hi2(v.z, v.w));
            }
        }
        __syncwarp();

        float c[8][4];
        u32 fh[4][4], fl[4][4];

        // ================= layer 1: x0[96] @ W1 -> 64 (1-term activations) =====
#pragma unroll
        for (int j = 0; j < 8; j++)
#pragma unroll
            for (int q = 0; q < 4; q++) c[j][q] = 0.f;
#pragma unroll
        for (int ks = 0; ks < 6; ks++) {
            int k0 = ks * 16;
            u32 aH[4];
            ldmx4(aH, smb + X0H + ((e0 + arow) * 104 + k0 + asel * 8) * 2);
#pragma unroll
            for (int jp = 0; jp < 8; jp += 2) {
                u32 addr = ((jp * 8 + brow) * 104 + k0) * 2 + boff;
                u32 bH[4];
                ldmx4(bH, smb + W1H + addr);
                mmafp(c[jp], aH, bH[0], bH[1]);
                mmafp(c[jp + 1], aH, bH[2], bH[3]);
            }
        }
        ln_frag(c, lnp, lnp + 64, lnp + 128, fh, fl, lane);

        // ================= layer 2: [h1(64), x0(96)] @ W2 -> 64 =================
#pragma unroll
        for (int j = 0; j < 8; j++)
#pragma unroll
            for (int q = 0; q < 4; q++) c[j][q] = 0.f;
        // h part (2-term, fragments already in registers)
#pragma unroll
        for (int ks = 0; ks < 4; ks++) {
            int kb = ks * 16;
#pragma unroll
            for (int jp = 0; jp < 8; jp += 2) {
                u32 addr = ((jp * 8 + brow) * 168 + kb) * 2 + boff;
                u32 bH[4];
                ldmx4(bH, smb + W2H + addr);
                mmafp(c[jp], fh[ks], bH[0], bH[1]);
                mmafp(c[jp], fl[ks], bH[0], bH[1]);
                mmafp(c[jp + 1], fh[ks], bH[2], bH[3]);
                mmafp(c[jp + 1], fl[ks], bH[2], bH[3]);
            }
        }
        // x0 part (1-term activations)
#pragma unroll
        for (int ks = 4; ks < 10; ks++) {
            int kb = ks * 16;
            u32 aH[4];
            ldmx4(aH, smb + X0H + ((e0 + arow) * 104 + (kb - 64) + asel * 8) * 2);
#pragma unroll
            for (int jp = 0; jp < 8; jp += 2) {
                u32 addr = ((jp * 8 + brow) * 168 + kb) * 2 + boff;
                u32 bH[4];
                ldmx4(bH, smb + W2H + addr);
                mmafp(c[jp], aH, bH[0], bH[1]);
                mmafp(c[jp + 1], aH, bH[2], bH[3]);
            }
        }
        ln_frag(c, lnp + 192, lnp + 256, lnp + 320, fh, fl, lane);

        // ================= layer 3: h2[64] @ W3 -> 32 (2-term) =================
        {
            float c3[4][4];
#pragma unroll
            for (int j = 0; j < 4; j++)
#pragma unroll
                for (int q = 0; q < 4; q++) c3[j][q] = 0.f;
#pragma unroll
            for (int ks = 0; ks < 4; ks++) {
                int k0 = ks * 16;
#pragma unroll
                for (int jp = 0; jp < 4; jp += 2) {
                    u32 addr = ((jp * 8 + brow) * 72 + k0) * 2 + boff;
                    u32 bH[4];
                    ldmx4(bH, smb + W3H + addr);
                    mmafp(c3[jp], fh[ks], bH[0], bH[1]);
                    mmafp(c3[jp], fl[ks], bH[0], bH[1]);
                    mmafp(c3[jp + 1], fh[ks], bH[2], bH[3]);
                    mmafp(c3[jp + 1], fl[ks], bH[2], bH[3]);
                }
            }
            // stage out tile in smem (+b3), then coalesced STG.128
#pragma unroll
            for (int j = 0; j < 4; j++) {
                int col = 8 * j + 2 * tg;
                float bb0 = lnp[384 + col], bb1 = lnp[384 + col + 1];
                *(float2*)(ob + gid * 36 + col) =
                    make_float2(c3[j][0] + bb0, c3[j][1] + bb1);
                *(float2*)(ob + (gid + 8) * 36 + col) =
                    make_float2(c3[j][2] + bb0, c3[j][3] + bb1);
            }
            __syncwarp();
#pragma unroll
            for (int it = 0; it < 4; it++) {
                int idx = it * 32 + lane;
                int row = idx >> 3, col4 = (idx & 7) * 4;
                int ge = eb + e0 + row;
                if (ge < E_TOTAL)
                    *(float4*)(out + (size_t)ge * 32 + col4) =
                        *(const float4*)(ob + row * 36 + col4);
            }
        }
    }
}

extern "C" void kernel_launch(void* const* d_in, const int* in_sizes, int n_in,
                              void* d_out, int out_size) {
    (void)in_sizes; (void)n_in; (void)out_size;
    const float* src = (const float*)d_in[0];
    const float* dst = (const float*)d_in[1];
    const float* ea  = (const float*)d_in[2];
    const float* W1  = (const float*)d_in[3];
    const float* b1  = (const float*)d_in[4];
    const float* g1  = (const float*)d_in[5];
    const float* be1 = (const float*)d_in[6];
    const float* W2  = (const float*)d_in[7];
    const float* b2  = (const float*)d_in[8];
    const float* g2  = (const float*)d_in[9];
    const float* be2 = (const float*)d_in[10];
    const float* W3  = (const float*)d_in[11];
    const float* b3  = (const float*)d_in[12];
    float* out = (float*)d_out;

    cudaFuncSetAttribute(EdgeModel_48636209660177_kernel,
                         cudaFuncAttributeMaxDynamicSharedMemorySize, SMEM_TOTAL);
    EdgeModel_48636209660177_kernel<<<GRID, THREADS, SMEM_TOTAL>>>(
        src, dst, ea, W1, b1, g1, be1, W2, b2, g2, be2, W3, b3, out);
}